// round 13
// baseline (speedup 1.0000x reference)
#include <cuda_runtime.h>
#include <cstdint>

#define KN   4096
#define LN   128
#define MEM  128
#define G4   512
#define NBLK 128
#define THR  512           /* 16 warps, one merged group, 32 arrays */

/* ---------------- device scratch ---------------- */
__device__ float d_Xt[LN * KN];
__device__ unsigned short d_W16[G4 * MEM];    /* f16(W_hh) row-major [gate row g][j] */
__device__ unsigned short d_Wf16[MEM * MEM];  /* f16(W_fh) */
__device__ float d_u[G4], d_v[G4];
__device__ float d_tabm[100], d_tabi[100], d_gm, d_gi;
__device__ float d_fcp[NBLK * MEM], d_hsp[NBLK * MEM];

/* ---------------- helpers ---------------- */
__device__ __forceinline__ uint32_t smem_u32(const void* p) {
    uint32_t a;
    asm("{ .reg .u64 t; cvta.to.shared.u64 t, %1; cvt.u32.u64 %0, t; }" : "=r"(a) : "l"(p));
    return a;
}
__device__ __forceinline__ float frcp(float x) { float r; asm("rcp.approx.f32 %0, %1;" : "=f"(r) : "f"(x)); return r; }
__device__ __forceinline__ float sigf(float x) { return frcp(1.0f + __expf(-x)); }
__device__ __forceinline__ float tanh_(float x) {
    float ax = fabsf(x);
    float e  = __expf(-2.0f * ax);
    float r  = (1.0f - e) * frcp(1.0f + e);
    return copysignf(r, x);
}
__device__ __forceinline__ float tanha(float x) {
    float r; asm("tanh.approx.f32 %0, %1;" : "=f"(r) : "f"(x)); return r;
}
/* packed f16x2 activations */
__device__ __forceinline__ unsigned tanh2(unsigned x) {
    unsigned r; asm("tanh.approx.f16x2 %0, %1;" : "=r"(r) : "r"(x)); return r;
}
__device__ __forceinline__ unsigned sig2(unsigned x) {   /* 0.5*tanh(0.5x)+0.5 */
    const unsigned H2 = 0x38003800u;
    unsigned t;
    asm("mul.rn.f16x2 %0, %1, %2;" : "=r"(t) : "r"(x), "r"(H2));
    t = tanh2(t);
    unsigned r;
    asm("fma.rn.f16x2 %0, %1, %2, %2;" : "=r"(r) : "r"(t), "r"(H2));
    return r;
}
__device__ __forceinline__ void up2(unsigned p, float& lo, float& hi) {
    asm("{ .reg .b16 a,b; mov.b32 {a,b}, %2; cvt.f32.f16 %0, a; cvt.f32.f16 %1, b; }"
        : "=f"(lo), "=f"(hi) : "r"(p));
}
__device__ __forceinline__ unsigned short f16b(float f) {
    unsigned short u; asm("cvt.rn.f16.f32 %0, %1;" : "=h"(u) : "f"(f)); return u;
}
__device__ __forceinline__ float f16tof(unsigned short u) {
    float f; asm("cvt.f32.f16 %0, %1;" : "=f"(f) : "h"(u)); return f;
}
__device__ __forceinline__ unsigned f16x2pk(float lo, float hi) {
    unsigned r; asm("cvt.rn.f16x2.f32 %0, %1, %2;" : "=r"(r) : "f"(hi), "f"(lo)); return r;
}
__device__ __forceinline__ void ldsm4t(uint32_t& r0, uint32_t& r1, uint32_t& r2, uint32_t& r3, uint32_t a) {
    asm volatile("ldmatrix.sync.aligned.m8n8.x4.trans.shared.b16 {%0,%1,%2,%3}, [%4];"
                 : "=r"(r0), "=r"(r1), "=r"(r2), "=r"(r3) : "r"(a));
}
__device__ __forceinline__ void mma_(float* d, const uint32_t* a, const uint32_t* b) {
    asm volatile("mma.sync.aligned.m16n8k16.row.col.f32.f16.f16.f32 "
                 "{%0,%1,%2,%3},{%4,%5,%6,%7},{%8,%9},{%0,%1,%2,%3};"
                 : "+f"(d[0]), "+f"(d[1]), "+f"(d[2]), "+f"(d[3])
                 : "r"(a[0]), "r"(a[1]), "r"(a[2]), "r"(a[3]), "r"(b[0]), "r"(b[1]));
}

/* -------- 1) running stats over first 100 flat numbers (smem-staged) -------- */
__global__ void k_stats(const float* __restrict__ nums) {
    __shared__ float s[100];
    __shared__ float scs[100], scss[100];
    int t = threadIdx.x;
    if (t < 100) s[t] = nums[t];
    __syncthreads();
    if (t == 0) {
        float cs = 0.0f, css = 0.0f;
        #pragma unroll 4
        for (int i = 0; i < 100; i++) {
            float x = s[i];
            cs += x; css += x * x;
            scs[i] = cs; scss[i] = css;
        }
    }
    __syncthreads();
    if (t < 100) {
        float cap  = (float)(t + 1);
        float mean = scs[t] / cap;
        float var  = fmaxf(scss[t] / cap - mean * mean, 0.0f);
        float sd   = sqrtf(var);
        bool  use  = (cap > 3.0f) && (sd > 1e-8f);
        float inv  = use ? (1.0f / sd) : 1.0f;
        d_tabm[t] = mean; d_tabi[t] = inv;
        if (t == 99) { d_gm = mean; d_gi = inv; }
    }
}

/* -------- 2) normalize + transpose -------- */
__global__ void k_norm(const float* __restrict__ nums) {
    int idx = blockIdx.x * blockDim.x + threadIdx.x;
    if (idx >= KN * LN) return;
    float x = nums[idx];
    float m, inv;
    if (idx < 100) { m = d_tabm[idx]; inv = d_tabi[idx]; }
    else           { m = d_gm;        inv = d_gi;        }
    int arr = idx >> 7, t = idx & 127;
    d_Xt[t * KN + arr] = (x - m) * inv;
}

/* -------- 3) weight prep: f16 weights + rank-1 input folding -------- */
__global__ void k_prep(const float* __restrict__ Wih, const float* __restrict__ Whh,
                       const float* __restrict__ bih, const float* __restrict__ bhh,
                       const float* __restrict__ Wfh, const float* __restrict__ wnum,
                       const float* __restrict__ bnum) {
    int idx = blockIdx.x * blockDim.x + threadIdx.x;
    if (idx < G4 * MEM) d_W16[idx] = f16b(Whh[idx]);
    int i2 = idx - G4 * MEM;
    if (i2 >= 0 && i2 < MEM * MEM) d_Wf16[i2] = f16b(Wfh[i2]);
    int i3 = idx - G4 * MEM - MEM * MEM;
    if (i3 >= 0 && i3 < G4) {
        const float* row = Wih + i3 * 256 + 128;
        float u = 0.0f, v = 0.0f;
        #pragma unroll 8
        for (int j = 0; j < 128; j++) { u += row[j] * wnum[j]; v += row[j] * bnum[j]; }
        d_u[i3] = u;
        d_v[i3] = v + bih[i3] + bhh[i3];
    }
}

/* -------- 4) main LSTM: register-resident W, f16x2 packed activations -------- */
/* warp w owns hidden units 8w..8w+8, all 4 gate banks. Thread (lid4,lm4) holds the
   full (i,f,g,o) quadruple for unit u=8w+lid4, arrays {nt*8+2lm4, +1}. */
__global__ void __launch_bounds__(THR, 1) k_lstm(const float* __restrict__ bfh) {
    __shared__ unsigned short shh[2][128 * 40];  /* h f16 [buf][unit j][array a], 80B row stride */
    __shared__ float shc[128 * 33];              /* final c [unit][array], padded */
    __shared__ float shred[2][128];

    const int tid = threadIdx.x;
    const int lid = tid & 31;
    const int w   = tid >> 5;
    const int lid4 = lid >> 2, lm4 = lid & 3;
    const int rl  = (lid & 7) | (((lid >> 3) & 1) << 3);
    const int ch  = lid >> 4;
    const int u   = 8 * w + lid4;                /* this thread's hidden unit */

    /* ---- A fragments of W_hh, loaded ONCE from global (64 regs) ---- */
    uint32_t A[2][8][4];
    #pragma unroll
    for (int mt = 0; mt < 2; mt++)
        #pragma unroll
        for (int kb = 0; kb < 8; kb++) {
            const unsigned short* r0 = &d_W16[((2 * mt)     * 128 + u) * 128 + kb * 16 + 2 * lm4];
            const unsigned short* r1 = &d_W16[((2 * mt + 1) * 128 + u) * 128 + kb * 16 + 2 * lm4];
            A[mt][kb][0] = *(const uint32_t*)r0;
            A[mt][kb][1] = *(const uint32_t*)r1;
            A[mt][kb][2] = *(const uint32_t*)(r0 + 8);
            A[mt][kb][3] = *(const uint32_t*)(r1 + 8);
        }

    float u4[4], v4[4];
    #pragma unroll
    for (int b = 0; b < 4; b++) { u4[b] = d_u[b * 128 + u]; v4[b] = d_v[b * 128 + u]; }

    float cst[8];
    #pragma unroll
    for (int i = 0; i < 8; i++) cst[i] = 0.0f;

    /* zero read buffer 0 */
    for (int p = tid; p < 2560; p += THR) ((uint32_t*)shh[0])[p] = 0u;
    __syncthreads();

    const uint32_t sb_h = smem_u32(shh);
    const uint32_t hLane = (uint32_t)rl * 80 + (uint32_t)ch * 16;
    const int gab = blockIdx.x * 32;

    for (int step = 0; step < LN; step++) {
        const uint32_t hRd = sb_h + (uint32_t)(step & 1) * 10240 + hLane;
        unsigned short* hw = shh[(step & 1) ^ 1];

        float acc[2][4][4];
        #pragma unroll
        for (int mt = 0; mt < 2; mt++)
            #pragma unroll
            for (int nt = 0; nt < 4; nt++)
                #pragma unroll
                for (int q = 0; q < 4; q++) acc[mt][nt][q] = 0.0f;

        #pragma unroll
        for (int kb = 0; kb < 8; kb++) {
            uint32_t B[4][2];
            {
                uint32_t q0, q1, q2, q3;
                ldsm4t(q0, q1, q2, q3, hRd + (uint32_t)kb * 1280);
                B[0][0] = q0; B[0][1] = q1; B[1][0] = q2; B[1][1] = q3;
                ldsm4t(q0, q1, q2, q3, hRd + (uint32_t)kb * 1280 + 32);
                B[2][0] = q0; B[2][1] = q1; B[3][0] = q2; B[3][1] = q3;
            }
            #pragma unroll
            for (int mt = 0; mt < 2; mt++)
                #pragma unroll
                for (int nt = 0; nt < 4; nt++)
                    mma_(acc[mt][nt], A[mt][kb], B[nt]);
        }

        /* epilogue: packed f16x2 activations (pair = the 2 arrays in this quadrant) */
        const float2* xp = (const float2*)&d_Xt[step * KN + gab];
        #pragma unroll
        for (int nt = 0; nt < 4; nt++) {
            float2 xv = __ldg(&xp[nt * 4 + lm4]);
            float gi0 = acc[0][nt][0] + fmaf(u4[0], xv.x, v4[0]);
            float gi1 = acc[0][nt][1] + fmaf(u4[0], xv.y, v4[0]);
            float gf0 = acc[0][nt][2] + fmaf(u4[1], xv.x, v4[1]);
            float gf1 = acc[0][nt][3] + fmaf(u4[1], xv.y, v4[1]);
            float gg0 = acc[1][nt][0] + fmaf(u4[2], xv.x, v4[2]);
            float gg1 = acc[1][nt][1] + fmaf(u4[2], xv.y, v4[2]);
            float go0 = acc[1][nt][2] + fmaf(u4[3], xv.x, v4[3]);
            float go1 = acc[1][nt][3] + fmaf(u4[3], xv.y, v4[3]);

            unsigned si = sig2(f16x2pk(gi0, gi1));
            unsigned sf = sig2(f16x2pk(gf0, gf1));
            unsigned so = sig2(f16x2pk(go0, go1));
            unsigned tg = tanh2(f16x2pk(gg0, gg1));

            float si0, si1, sf0, sf1, so0, so1, tg0, tg1;
            up2(si, si0, si1);
            up2(sf, sf0, sf1);
            up2(so, so0, so1);
            up2(tg, tg0, tg1);

            float c20 = sf0 * cst[nt * 2 + 0] + si0 * tg0;
            float c21 = sf1 * cst[nt * 2 + 1] + si1 * tg1;
            float h0  = so0 * tanha(c20);
            float h1  = so1 * tanha(c21);
            cst[nt * 2 + 0] = c20;
            cst[nt * 2 + 1] = c21;
            *(unsigned*)&hw[u * 40 + nt * 8 + 2 * lm4] = f16x2pk(h0, h1);
        }
        __syncthreads();
    }

    /* ---- stage c to smem for the f-gate pass ---- */
    #pragma unroll
    for (int nt = 0; nt < 4; nt++) {
        shc[u * 33 + nt * 8 + 2 * lm4]     = cst[nt * 2 + 0];
        shc[u * 33 + nt * 8 + 2 * lm4 + 1] = cst[nt * 2 + 1];
    }
    __syncthreads();

    /* ---- f-gate GEMM: warp w -> m16 tile (w&7), n-half (w>>3) ---- */
    const int mt = w & 7, nh = w >> 3;
    uint32_t Af[8][4];
    #pragma unroll
    for (int kb = 0; kb < 8; kb++) {
        const unsigned short* r0 = &d_Wf16[(16 * mt + lid4) * 128 + kb * 16 + 2 * lm4];
        const unsigned short* r1 = r0 + 8 * 128;
        Af[kb][0] = *(const uint32_t*)r0;
        Af[kb][1] = *(const uint32_t*)r1;
        Af[kb][2] = *(const uint32_t*)(r0 + 8);
        Af[kb][3] = *(const uint32_t*)(r1 + 8);
    }
    float fa[2][4];
    #pragma unroll
    for (int nt = 0; nt < 2; nt++)
        #pragma unroll
        for (int q = 0; q < 4; q++) fa[nt][q] = 0.0f;
    const uint32_t hF = sb_h + hLane + (uint32_t)nh * 32;   /* final h is in buffer 0 */
    #pragma unroll
    for (int kb = 0; kb < 8; kb++) {
        uint32_t q0, q1, q2, q3;
        ldsm4t(q0, q1, q2, q3, hF + (uint32_t)kb * 1280);
        uint32_t B0[2] = {q0, q1}, B1[2] = {q2, q3};
        mma_(fa[0], Af[kb], B0);
        mma_(fa[1], Af[kb], B1);
    }
    const int r0 = 16 * mt + lid4, r1 = r0 + 8;
    float b0 = bfh[r0], b1 = bfh[r1];
    float f0 = 0.0f, f1 = 0.0f;
    #pragma unroll
    for (int nt = 0; nt < 2; nt++)
        #pragma unroll
        for (int q = 0; q < 2; q++) {
            int col = nh * 16 + nt * 8 + 2 * lm4 + q;
            f0 += sigf(fa[nt][q]     + b0) * shc[r0 * 33 + col];
            f1 += sigf(fa[nt][2 + q] + b1) * shc[r1 * 33 + col];
        }
    f0 += __shfl_xor_sync(0xFFFFFFFFu, f0, 1);
    f0 += __shfl_xor_sync(0xFFFFFFFFu, f0, 2);
    f1 += __shfl_xor_sync(0xFFFFFFFFu, f1, 1);
    f1 += __shfl_xor_sync(0xFFFFFFFFu, f1, 2);
    if (lm4 == 0) { shred[nh][r0] = f0; shred[nh][r1] = f1; }
    __syncthreads();

    if (tid < 128) {
        float fc = shred[0][tid] + shred[1][tid];
        float hs = 0.0f;
        #pragma unroll 8
        for (int a = 0; a < 32; a++) hs += f16tof(shh[0][tid * 40 + a]);
        d_fcp[blockIdx.x * MEM + tid] = fc;
        d_hsp[blockIdx.x * MEM + tid] = hs;
    }
}

/* -------- 5) final tree-LSTM root math -------- */
__global__ void k_final(const float* __restrict__ Wiou, const float* __restrict__ biou,
                        const float* __restrict__ Wlout, const float* __restrict__ blout,
                        float* __restrict__ out) {
    __shared__ float sh_hs[128];
    __shared__ float sh_h[128];
    int k = threadIdx.x;
    float fc = 0.0f, hs = 0.0f;
    for (int b = 0; b < NBLK; b++) {
        fc += d_fcp[b * MEM + k];
        hs += d_hsp[b * MEM + k];
    }
    sh_hs[k] = hs;
    __syncthreads();
    float iv = biou[k], ov = biou[128 + k], uv = biou[256 + k];
    #pragma unroll 8
    for (int j = 0; j < 128; j++) {
        float h = sh_hs[j];
        iv += Wiou[k * 128 + j] * h;
        ov += Wiou[(128 + k) * 128 + j] * h;
        uv += Wiou[(256 + k) * 128 + j] * h;
    }
    float cv = sigf(iv) * tanh_(uv) + fc;
    float hv = sigf(ov) * tanh_(cv);
    out[k]  = cv;
    sh_h[k] = hv;
    __syncthreads();
    float acc = blout[k];
    #pragma unroll 8
    for (int j = 0; j < 128; j++) acc += Wlout[k * 128 + j] * sh_h[j];
    out[128 + k] = acc;
}

extern "C" void kernel_launch(void* const* d_in, const int* in_sizes, int n_in,
                              void* d_out, int out_size) {
    const float* numbers = (const float*)d_in[0];
    const float* wnum    = (const float*)d_in[1];
    const float* bnum    = (const float*)d_in[2];
    const float* Wih     = (const float*)d_in[3];
    const float* Whh     = (const float*)d_in[4];
    const float* bih     = (const float*)d_in[5];
    const float* bhh     = (const float*)d_in[6];
    const float* Wfh     = (const float*)d_in[7];
    const float* bfh     = (const float*)d_in[8];
    const float* Wiou    = (const float*)d_in[9];
    const float* biou    = (const float*)d_in[10];
    const float* Wlout   = (const float*)d_in[11];
    const float* blout   = (const float*)d_in[12];
    float* out = (float*)d_out;

    k_stats<<<1, 128>>>(numbers);
    k_norm<<<(KN * LN + 255) / 256, 256>>>(numbers);
    k_prep<<<(G4 * MEM + MEM * MEM + G4 + 255) / 256, 256>>>(Wih, Whh, bih, bhh, Wfh, wnum, bnum);
    k_lstm<<<NBLK, THR>>>(bfh);
    k_final<<<1, 128>>>(Wiou, biou, Wlout, blout, out);
}

// round 14
// speedup vs baseline: 1.0982x; 1.0982x over previous
#include <cuda_runtime.h>
#include <cstdint>

#define KN   4096
#define LN   128
#define MEM  128
#define G4   512
#define NBLK 128
#define THR  512           /* 16 warps, 32 arrays, halves pipelined */

/* dynamic smem layout (bytes) */
#define SHH_OFF  0          /* 20480: h f16 [2 buf][128 unit][40 pad arrays] */
#define SX_OFF   20480      /* 16384: x tile f32 [128 step][32 array] */
#define SHC_OFF  36864      /* 16896: final c [128][33] */
#define SHRED_OFF 53760     /* 1024 : f-gate partial reduction [2][128] */
#define SMEM_TOTAL 54784

/* ---------------- device scratch ---------------- */
__device__ float d_Xt[LN * KN];
__device__ unsigned short d_W16[G4 * MEM];    /* f16(W_hh) row-major [gate row g][j] */
__device__ unsigned short d_Wf16[MEM * MEM];  /* f16(W_fh) */
__device__ float d_u[G4], d_v[G4];
__device__ float d_tabm[100], d_tabi[100], d_gm, d_gi;
__device__ float d_fcp[NBLK * MEM], d_hsp[NBLK * MEM];

/* ---------------- helpers ---------------- */
__device__ __forceinline__ uint32_t smem_u32(const void* p) {
    uint32_t a;
    asm("{ .reg .u64 t; cvta.to.shared.u64 t, %1; cvt.u32.u64 %0, t; }" : "=r"(a) : "l"(p));
    return a;
}
__device__ __forceinline__ float frcp(float x) { float r; asm("rcp.approx.f32 %0, %1;" : "=f"(r) : "f"(x)); return r; }
__device__ __forceinline__ float sigf(float x) { return frcp(1.0f + __expf(-x)); }
__device__ __forceinline__ float tanh_(float x) {
    float ax = fabsf(x);
    float e  = __expf(-2.0f * ax);
    float r  = (1.0f - e) * frcp(1.0f + e);
    return copysignf(r, x);
}
__device__ __forceinline__ float tanha(float x) {
    float r; asm("tanh.approx.f32 %0, %1;" : "=f"(r) : "f"(x)); return r;
}
__device__ __forceinline__ float siga(float x) {
    return fmaf(tanha(0.5f * x), 0.5f, 0.5f);
}
__device__ __forceinline__ unsigned short f16b(float f) {
    unsigned short u; asm("cvt.rn.f16.f32 %0, %1;" : "=h"(u) : "f"(f)); return u;
}
__device__ __forceinline__ float f16tof(unsigned short u) {
    float f; asm("cvt.f32.f16 %0, %1;" : "=f"(f) : "h"(u)); return f;
}
__device__ __forceinline__ unsigned f16x2pk(float lo, float hi) {
    unsigned r; asm("cvt.rn.f16x2.f32 %0, %1, %2;" : "=r"(r) : "f"(hi), "f"(lo)); return r;
}
__device__ __forceinline__ void ldsm4t(uint32_t& r0, uint32_t& r1, uint32_t& r2, uint32_t& r3, uint32_t a) {
    asm volatile("ldmatrix.sync.aligned.m8n8.x4.trans.shared.b16 {%0,%1,%2,%3}, [%4];"
                 : "=r"(r0), "=r"(r1), "=r"(r2), "=r"(r3) : "r"(a));
}
__device__ __forceinline__ void mma_(float* d, const uint32_t* a, const uint32_t* b) {
    asm volatile("mma.sync.aligned.m16n8k16.row.col.f32.f16.f16.f32 "
                 "{%0,%1,%2,%3},{%4,%5,%6,%7},{%8,%9},{%0,%1,%2,%3};"
                 : "+f"(d[0]), "+f"(d[1]), "+f"(d[2]), "+f"(d[3])
                 : "r"(a[0]), "r"(a[1]), "r"(a[2]), "r"(a[3]), "r"(b[0]), "r"(b[1]));
}

/* -------- 1) running stats over first 100 flat numbers (smem-staged) -------- */
__global__ void k_stats(const float* __restrict__ nums) {
    __shared__ float s[100];
    __shared__ float scs[100], scss[100];
    int t = threadIdx.x;
    if (t < 100) s[t] = nums[t];
    __syncthreads();
    if (t == 0) {
        float cs = 0.0f, css = 0.0f;
        #pragma unroll 4
        for (int i = 0; i < 100; i++) {
            float x = s[i];
            cs += x; css += x * x;
            scs[i] = cs; scss[i] = css;
        }
    }
    __syncthreads();
    if (t < 100) {
        float cap  = (float)(t + 1);
        float mean = scs[t] / cap;
        float var  = fmaxf(scss[t] / cap - mean * mean, 0.0f);
        float sd   = sqrtf(var);
        bool  use  = (cap > 3.0f) && (sd > 1e-8f);
        float inv  = use ? (1.0f / sd) : 1.0f;
        d_tabm[t] = mean; d_tabi[t] = inv;
        if (t == 99) { d_gm = mean; d_gi = inv; }
    }
}

/* -------- 2) normalize + transpose -------- */
__global__ void k_norm(const float* __restrict__ nums) {
    int idx = blockIdx.x * blockDim.x + threadIdx.x;
    if (idx >= KN * LN) return;
    float x = nums[idx];
    float m, inv;
    if (idx < 100) { m = d_tabm[idx]; inv = d_tabi[idx]; }
    else           { m = d_gm;        inv = d_gi;        }
    int arr = idx >> 7, t = idx & 127;
    d_Xt[t * KN + arr] = (x - m) * inv;
}

/* -------- 3) weight prep: f16 weights + rank-1 input folding -------- */
__global__ void k_prep(const float* __restrict__ Wih, const float* __restrict__ Whh,
                       const float* __restrict__ bih, const float* __restrict__ bhh,
                       const float* __restrict__ Wfh, const float* __restrict__ wnum,
                       const float* __restrict__ bnum) {
    int idx = blockIdx.x * blockDim.x + threadIdx.x;
    if (idx < G4 * MEM) d_W16[idx] = f16b(Whh[idx]);
    int i2 = idx - G4 * MEM;
    if (i2 >= 0 && i2 < MEM * MEM) d_Wf16[i2] = f16b(Wfh[i2]);
    int i3 = idx - G4 * MEM - MEM * MEM;
    if (i3 >= 0 && i3 < G4) {
        const float* row = Wih + i3 * 256 + 128;
        float u = 0.0f, v = 0.0f;
        #pragma unroll 8
        for (int j = 0; j < 128; j++) { u += row[j] * wnum[j]; v += row[j] * bnum[j]; }
        d_u[i3] = u;
        d_v[i3] = v + bih[i3] + bhh[i3];
    }
}

/* -------- 4) main LSTM: register-resident W, half-step pipelined halves -------- */
/* warp w owns hidden units 8w..8w+8, all 4 gate banks. Thread (lid4,lm4) holds the
   full (i,f,g,o) quadruple for unit u=8w+lid4, arrays {half*16 + ntl*8 + 2lm4, +1}.
   Halves (arrays 0-15 / 16-31) are independent recurrences: issue MMA for one half,
   then run the other half's activation epilogue while the tensor pipe works. */

#define ZACC(accH) do { \
    _Pragma("unroll") for (int _m = 0; _m < 2; _m++) \
    _Pragma("unroll") for (int _n = 0; _n < 2; _n++) \
    _Pragma("unroll") for (int _q = 0; _q < 4; _q++) accH[_m][_n][_q] = 0.0f; \
} while (0)

#define MMA_HALF(accH, parity, colOff) do { \
    uint32_t _hRd = sb_h + (uint32_t)(parity) * 10240u + hLane + (colOff); \
    _Pragma("unroll") \
    for (int _kb = 0; _kb < 8; _kb++) { \
        uint32_t _q0, _q1, _q2, _q3; \
        ldsm4t(_q0, _q1, _q2, _q3, _hRd + (uint32_t)_kb * 1280u); \
        uint32_t _B0[2] = {_q0, _q1}, _B1[2] = {_q2, _q3}; \
        mma_(accH[0][0], A[0][_kb], _B0); \
        mma_(accH[1][0], A[1][_kb], _B0); \
        mma_(accH[0][1], A[0][_kb], _B1); \
        mma_(accH[1][1], A[1][_kb], _B1); \
    } \
} while (0)

#define EPI_HALF(accH, cstH, half, tt, wparity) do { \
    unsigned short* _hw = (unsigned short*)(dsm + SHH_OFF) + (size_t)(wparity) * 5120; \
    _Pragma("unroll") \
    for (int _nt = 0; _nt < 2; _nt++) { \
        float2 _xv = sx2[(tt) * 16 + (half) * 8 + _nt * 4 + lm4]; \
        float _gi0 = accH[0][_nt][0] + fmaf(u4[0], _xv.x, v4[0]); \
        float _gi1 = accH[0][_nt][1] + fmaf(u4[0], _xv.y, v4[0]); \
        float _gf0 = accH[0][_nt][2] + fmaf(u4[1], _xv.x, v4[1]); \
        float _gf1 = accH[0][_nt][3] + fmaf(u4[1], _xv.y, v4[1]); \
        float _gg0 = accH[1][_nt][0] + fmaf(u4[2], _xv.x, v4[2]); \
        float _gg1 = accH[1][_nt][1] + fmaf(u4[2], _xv.y, v4[2]); \
        float _go0 = accH[1][_nt][2] + fmaf(u4[3], _xv.x, v4[3]); \
        float _go1 = accH[1][_nt][3] + fmaf(u4[3], _xv.y, v4[3]); \
        float _c20 = siga(_gf0) * cstH[_nt * 2 + 0] + siga(_gi0) * tanha(_gg0); \
        float _c21 = siga(_gf1) * cstH[_nt * 2 + 1] + siga(_gi1) * tanha(_gg1); \
        float _h0  = siga(_go0) * tanha(_c20); \
        float _h1  = siga(_go1) * tanha(_c21); \
        cstH[_nt * 2 + 0] = _c20; cstH[_nt * 2 + 1] = _c21; \
        *(unsigned*)&_hw[u * 40 + ((half) * 2 + _nt) * 8 + 2 * lm4] = f16x2pk(_h0, _h1); \
    } \
} while (0)

__global__ void __launch_bounds__(THR, 1) k_lstm(const float* __restrict__ bfh) {
    extern __shared__ char dsm[];

    const int tid = threadIdx.x;
    const int lid = tid & 31;
    const int w   = tid >> 5;
    const int lid4 = lid >> 2, lm4 = lid & 3;
    const int rl  = (lid & 7) | (((lid >> 3) & 1) << 3);
    const int ch  = lid >> 4;
    const int u   = 8 * w + lid4;                /* this thread's hidden unit */
    const int gab = blockIdx.x * 32;

    /* ---- A fragments of W_hh, loaded ONCE from global (64 regs) ---- */
    uint32_t A[2][8][4];
    #pragma unroll
    for (int mt = 0; mt < 2; mt++)
        #pragma unroll
        for (int kb = 0; kb < 8; kb++) {
            const unsigned short* r0 = &d_W16[((2 * mt)     * 128 + u) * 128 + kb * 16 + 2 * lm4];
            const unsigned short* r1 = &d_W16[((2 * mt + 1) * 128 + u) * 128 + kb * 16 + 2 * lm4];
            A[mt][kb][0] = *(const uint32_t*)r0;
            A[mt][kb][1] = *(const uint32_t*)r1;
            A[mt][kb][2] = *(const uint32_t*)(r0 + 8);
            A[mt][kb][3] = *(const uint32_t*)(r1 + 8);
        }

    float u4[4], v4[4];
    #pragma unroll
    for (int b = 0; b < 4; b++) { u4[b] = d_u[b * 128 + u]; v4[b] = d_v[b * 128 + u]; }

    float cstA[4], cstB[4];
    #pragma unroll
    for (int i = 0; i < 4; i++) { cstA[i] = 0.0f; cstB[i] = 0.0f; }

    /* zero h read-buffer 0; stage this block's whole X tile into smem */
    for (int p = tid; p < 2560; p += THR)
        ((uint32_t*)(dsm + SHH_OFF))[p] = 0u;
    {
        float* sxf = (float*)(dsm + SX_OFF);
        for (int i = tid; i < 4096; i += THR)
            sxf[i] = d_Xt[(i >> 5) * KN + gab + (i & 31)];
    }
    __syncthreads();

    const uint32_t sb_h = smem_u32(dsm + SHH_OFF);
    const uint32_t hLane = (uint32_t)rl * 80 + (uint32_t)ch * 16;
    const float2* sx2 = (const float2*)(dsm + SX_OFF);

    float accA[2][2][4], accB[2][2][4];

    /* prologue: step 0 */
    ZACC(accA); MMA_HALF(accA, 0, 0u);            /* MMA_A(0) reads buf0 (zeros) */
    __syncthreads();                               /* barB */
    ZACC(accB); MMA_HALF(accB, 0, 32u);           /* MMA_B(0) */
    EPI_HALF(accA, cstA, 0, 0, 1);                /* EPI_A(0) -> buf1 cols A */

    for (int t = 1; t < LN; t++) {
        __syncthreads();                           /* barA: h_A(t-1) complete */
        ZACC(accA); MMA_HALF(accA, t & 1, 0u);    /* MMA_A(t), async on tensor */
        EPI_HALF(accB, cstB, 1, t - 1, t & 1);    /* EPI_B(t-1), overlaps MMA_A */
        __syncthreads();                           /* barB: h_B(t-1) complete */
        ZACC(accB); MMA_HALF(accB, t & 1, 32u);   /* MMA_B(t), async on tensor */
        EPI_HALF(accA, cstA, 0, t, (t & 1) ^ 1);  /* EPI_A(t), overlaps MMA_B */
    }
    EPI_HALF(accB, cstB, 1, LN - 1, 0);           /* tail: EPI_B(127) -> buf0 */
    __syncthreads();                               /* final h (both halves) in buf0 */

    /* ---- stage c to smem for the f-gate pass ---- */
    float* shc = (float*)(dsm + SHC_OFF);
    #pragma unroll
    for (int nt = 0; nt < 2; nt++) {
        shc[u * 33 + nt * 8 + 2 * lm4]          = cstA[nt * 2 + 0];
        shc[u * 33 + nt * 8 + 2 * lm4 + 1]      = cstA[nt * 2 + 1];
        shc[u * 33 + 16 + nt * 8 + 2 * lm4]     = cstB[nt * 2 + 0];
        shc[u * 33 + 16 + nt * 8 + 2 * lm4 + 1] = cstB[nt * 2 + 1];
    }
    __syncthreads();

    /* ---- f-gate GEMM: warp w -> m16 tile (w&7), n-half (w>>3) ---- */
    const int mt = w & 7, nh = w >> 3;
    uint32_t Af[8][4];
    #pragma unroll
    for (int kb = 0; kb < 8; kb++) {
        const unsigned short* r0 = &d_Wf16[(16 * mt + lid4) * 128 + kb * 16 + 2 * lm4];
        const unsigned short* r1 = r0 + 8 * 128;
        Af[kb][0] = *(const uint32_t*)r0;
        Af[kb][1] = *(const uint32_t*)r1;
        Af[kb][2] = *(const uint32_t*)(r0 + 8);
        Af[kb][3] = *(const uint32_t*)(r1 + 8);
    }
    float fa[2][4];
    #pragma unroll
    for (int nt = 0; nt < 2; nt++)
        #pragma unroll
        for (int q = 0; q < 4; q++) fa[nt][q] = 0.0f;
    const uint32_t hF = sb_h + hLane + (uint32_t)nh * 32;   /* final h in buffer 0 */
    #pragma unroll
    for (int kb = 0; kb < 8; kb++) {
        uint32_t q0, q1, q2, q3;
        ldsm4t(q0, q1, q2, q3, hF + (uint32_t)kb * 1280);
        uint32_t B0[2] = {q0, q1}, B1[2] = {q2, q3};
        mma_(fa[0], Af[kb], B0);
        mma_(fa[1], Af[kb], B1);
    }
    const int r0 = 16 * mt + lid4, r1 = r0 + 8;
    float b0 = bfh[r0], b1 = bfh[r1];
    float f0 = 0.0f, f1 = 0.0f;
    #pragma unroll
    for (int nt = 0; nt < 2; nt++)
        #pragma unroll
        for (int q = 0; q < 2; q++) {
            int col = nh * 16 + nt * 8 + 2 * lm4 + q;
            f0 += sigf(fa[nt][q]     + b0) * shc[r0 * 33 + col];
            f1 += sigf(fa[nt][2 + q] + b1) * shc[r1 * 33 + col];
        }
    f0 += __shfl_xor_sync(0xFFFFFFFFu, f0, 1);
    f0 += __shfl_xor_sync(0xFFFFFFFFu, f0, 2);
    f1 += __shfl_xor_sync(0xFFFFFFFFu, f1, 1);
    f1 += __shfl_xor_sync(0xFFFFFFFFu, f1, 2);
    float* shred = (float*)(dsm + SHRED_OFF);
    if (lm4 == 0) { shred[nh * 128 + r0] = f0; shred[nh * 128 + r1] = f1; }
    __syncthreads();

    if (tid < 128) {
        float fc = shred[tid] + shred[128 + tid];
        float hs = 0.0f;
        const unsigned short* h0 = (const unsigned short*)(dsm + SHH_OFF);
        #pragma unroll 8
        for (int a = 0; a < 32; a++) hs += f16tof(h0[tid * 40 + a]);
        d_fcp[blockIdx.x * MEM + tid] = fc;
        d_hsp[blockIdx.x * MEM + tid] = hs;
    }
}

/* -------- 5) final tree-LSTM root math -------- */
__global__ void k_final(const float* __restrict__ Wiou, const float* __restrict__ biou,
                        const float* __restrict__ Wlout, const float* __restrict__ blout,
                        float* __restrict__ out) {
    __shared__ float sh_hs[128];
    __shared__ float sh_h[128];
    int k = threadIdx.x;
    float fc = 0.0f, hs = 0.0f;
    for (int b = 0; b < NBLK; b++) {
        fc += d_fcp[b * MEM + k];
        hs += d_hsp[b * MEM + k];
    }
    sh_hs[k] = hs;
    __syncthreads();
    float iv = biou[k], ov = biou[128 + k], uv = biou[256 + k];
    #pragma unroll 8
    for (int j = 0; j < 128; j++) {
        float h = sh_hs[j];
        iv += Wiou[k * 128 + j] * h;
        ov += Wiou[(128 + k) * 128 + j] * h;
        uv += Wiou[(256 + k) * 128 + j] * h;
    }
    float cv = sigf(iv) * tanh_(uv) + fc;
    float hv = sigf(ov) * tanh_(cv);
    out[k]  = cv;
    sh_h[k] = hv;
    __syncthreads();
    float acc = blout[k];
    #pragma unroll 8
    for (int j = 0; j < 128; j++) acc += Wlout[k * 128 + j] * sh_h[j];
    out[128 + k] = acc;
}

extern "C" void kernel_launch(void* const* d_in, const int* in_sizes, int n_in,
                              void* d_out, int out_size) {
    const float* numbers = (const float*)d_in[0];
    const float* wnum    = (const float*)d_in[1];
    const float* bnum    = (const float*)d_in[2];
    const float* Wih     = (const float*)d_in[3];
    const float* Whh     = (const float*)d_in[4];
    const float* bih     = (const float*)d_in[5];
    const float* bhh     = (const float*)d_in[6];
    const float* Wfh     = (const float*)d_in[7];
    const float* bfh     = (const float*)d_in[8];
    const float* Wiou    = (const float*)d_in[9];
    const float* biou    = (const float*)d_in[10];
    const float* Wlout   = (const float*)d_in[11];
    const float* blout   = (const float*)d_in[12];
    float* out = (float*)d_out;

    cudaFuncSetAttribute(k_lstm, cudaFuncAttributeMaxDynamicSharedMemorySize, SMEM_TOTAL);

    k_stats<<<1, 128>>>(numbers);
    k_norm<<<(KN * LN + 255) / 256, 256>>>(numbers);
    k_prep<<<(G4 * MEM + MEM * MEM + G4 + 255) / 256, 256>>>(Wih, Whh, bih, bhh, Wfh, wnum, bnum);
    k_lstm<<<NBLK, THR, SMEM_TOTAL>>>(bfh);
    k_final<<<1, 128>>>(Wiou, biou, Wlout, blout, out);
}

// round 15
// speedup vs baseline: 1.1387x; 1.0368x over previous
#include <cuda_runtime.h>
#include <cstdint>

#define KN   4096
#define LN   128
#define MEM  128
#define G4   512
#define NBLK 128
#define THR  512           /* 16 warps, 32 arrays, halves pipelined */

/* dynamic smem layout (bytes) */
#define SHH_OFF  0          /* 20480: h f16 [2 buf][128 unit][40 pad arrays] */
#define SX_OFF   20480      /* 16384: x tile f32 [128 step][32 array] */
#define SHC_OFF  36864      /* 16896: final c [128][33] */
#define SHRED_OFF 53760     /* 1024 : f-gate partial reduction [2][128] */
#define SMEM_TOTAL 54784

/* ---------------- device scratch ---------------- */
__device__ float d_Xt[LN * KN];
__device__ unsigned short d_W16[G4 * MEM];    /* f16(W_hh) row-major [gate row g][j] */
__device__ unsigned short d_Wf16[MEM * MEM];  /* f16(W_fh) */
__device__ float d_u[G4], d_v[G4];
__device__ float d_tabm[100], d_tabi[100], d_gm, d_gi;
__device__ float d_fcp[NBLK * MEM], d_hsp[NBLK * MEM];

/* ---------------- helpers ---------------- */
__device__ __forceinline__ uint32_t smem_u32(const void* p) {
    uint32_t a;
    asm("{ .reg .u64 t; cvta.to.shared.u64 t, %1; cvt.u32.u64 %0, t; }" : "=r"(a) : "l"(p));
    return a;
}
__device__ __forceinline__ float frcp(float x) { float r; asm("rcp.approx.f32 %0, %1;" : "=f"(r) : "f"(x)); return r; }
__device__ __forceinline__ float sigf(float x) { return frcp(1.0f + __expf(-x)); }
__device__ __forceinline__ float tanh_(float x) {
    float ax = fabsf(x);
    float e  = __expf(-2.0f * ax);
    float r  = (1.0f - e) * frcp(1.0f + e);
    return copysignf(r, x);
}
__device__ __forceinline__ float tanha(float x) {
    float r; asm("tanh.approx.f32 %0, %1;" : "=f"(r) : "f"(x)); return r;
}
/* packed f16x2 sigmoid: 0.5*tanh(0.5x)+0.5 */
__device__ __forceinline__ unsigned tanh2(unsigned x) {
    unsigned r; asm("tanh.approx.f16x2 %0, %1;" : "=r"(r) : "r"(x)); return r;
}
__device__ __forceinline__ unsigned sig2(unsigned x) {
    const unsigned H2 = 0x38003800u;
    unsigned t;
    asm("mul.rn.f16x2 %0, %1, %2;" : "=r"(t) : "r"(x), "r"(H2));
    t = tanh2(t);
    unsigned r;
    asm("fma.rn.f16x2 %0, %1, %2, %2;" : "=r"(r) : "r"(t), "r"(H2));
    return r;
}
__device__ __forceinline__ void up2(unsigned p, float& lo, float& hi) {
    asm("{ .reg .b16 a,b; mov.b32 {a,b}, %2; cvt.f32.f16 %0, a; cvt.f32.f16 %1, b; }"
        : "=f"(lo), "=f"(hi) : "r"(p));
}
__device__ __forceinline__ unsigned short f16b(float f) {
    unsigned short u; asm("cvt.rn.f16.f32 %0, %1;" : "=h"(u) : "f"(f)); return u;
}
__device__ __forceinline__ float f16tof(unsigned short u) {
    float f; asm("cvt.f32.f16 %0, %1;" : "=f"(f) : "h"(u)); return f;
}
__device__ __forceinline__ unsigned f16x2pk(float lo, float hi) {
    unsigned r; asm("cvt.rn.f16x2.f32 %0, %1, %2;" : "=r"(r) : "f"(hi), "f"(lo)); return r;
}
__device__ __forceinline__ void ldsm4t(uint32_t& r0, uint32_t& r1, uint32_t& r2, uint32_t& r3, uint32_t a) {
    asm volatile("ldmatrix.sync.aligned.m8n8.x4.trans.shared.b16 {%0,%1,%2,%3}, [%4];"
                 : "=r"(r0), "=r"(r1), "=r"(r2), "=r"(r3) : "r"(a));
}
__device__ __forceinline__ void mma_(float* d, const uint32_t* a, const uint32_t* b) {
    asm volatile("mma.sync.aligned.m16n8k16.row.col.f32.f16.f16.f32 "
                 "{%0,%1,%2,%3},{%4,%5,%6,%7},{%8,%9},{%0,%1,%2,%3};"
                 : "+f"(d[0]), "+f"(d[1]), "+f"(d[2]), "+f"(d[3])
                 : "r"(a[0]), "r"(a[1]), "r"(a[2]), "r"(a[3]), "r"(b[0]), "r"(b[1]));
}

/* -------- 1) running stats over first 100 flat numbers (smem-staged) -------- */
__global__ void k_stats(const float* __restrict__ nums) {
    __shared__ float s[100];
    __shared__ float scs[100], scss[100];
    int t = threadIdx.x;
    if (t < 100) s[t] = nums[t];
    __syncthreads();
    if (t == 0) {
        float cs = 0.0f, css = 0.0f;
        #pragma unroll 4
        for (int i = 0; i < 100; i++) {
            float x = s[i];
            cs += x; css += x * x;
            scs[i] = cs; scss[i] = css;
        }
    }
    __syncthreads();
    if (t < 100) {
        float cap  = (float)(t + 1);
        float mean = scs[t] / cap;
        float var  = fmaxf(scss[t] / cap - mean * mean, 0.0f);
        float sd   = sqrtf(var);
        bool  use  = (cap > 3.0f) && (sd > 1e-8f);
        float inv  = use ? (1.0f / sd) : 1.0f;
        d_tabm[t] = mean; d_tabi[t] = inv;
        if (t == 99) { d_gm = mean; d_gi = inv; }
    }
}

/* -------- 2) normalize + transpose -------- */
__global__ void k_norm(const float* __restrict__ nums) {
    int idx = blockIdx.x * blockDim.x + threadIdx.x;
    if (idx >= KN * LN) return;
    float x = nums[idx];
    float m, inv;
    if (idx < 100) { m = d_tabm[idx]; inv = d_tabi[idx]; }
    else           { m = d_gm;        inv = d_gi;        }
    int arr = idx >> 7, t = idx & 127;
    d_Xt[t * KN + arr] = (x - m) * inv;
}

/* -------- 3) weight prep: f16 weights + rank-1 input folding -------- */
__global__ void k_prep(const float* __restrict__ Wih, const float* __restrict__ Whh,
                       const float* __restrict__ bih, const float* __restrict__ bhh,
                       const float* __restrict__ Wfh, const float* __restrict__ wnum,
                       const float* __restrict__ bnum) {
    int idx = blockIdx.x * blockDim.x + threadIdx.x;
    if (idx < G4 * MEM) d_W16[idx] = f16b(Whh[idx]);
    int i2 = idx - G4 * MEM;
    if (i2 >= 0 && i2 < MEM * MEM) d_Wf16[i2] = f16b(Wfh[i2]);
    int i3 = idx - G4 * MEM - MEM * MEM;
    if (i3 >= 0 && i3 < G4) {
        const float* row = Wih + i3 * 256 + 128;
        float u = 0.0f, v = 0.0f;
        #pragma unroll 8
        for (int j = 0; j < 128; j++) { u += row[j] * wnum[j]; v += row[j] * bnum[j]; }
        d_u[i3] = u;
        d_v[i3] = v + bih[i3] + bhh[i3];
    }
}

/* -------- 4) main LSTM: register-resident W, half-step pipelined halves -------- */
/* warp w owns hidden units 8w..8w+8, all 4 gate banks. Thread (lid4,lm4) holds the
   full (i,f,g,o) quadruple for unit u=8w+lid4, arrays {half*16 + ntl*8 + 2lm4, +1}.
   Accumulators are INITIALIZED with the exact fp32 input term u*x+v (replaces both
   the zero-init MOVs and the epilogue gate-adds); MMA adds W_hh@h on top. */

#define INIT_ACC(accH, half, tt) do { \
    _Pragma("unroll") \
    for (int _nt = 0; _nt < 2; _nt++) { \
        float2 _xv = sx2[(tt) * 16 + (half) * 8 + _nt * 4 + lm4]; \
        accH[0][_nt][0] = fmaf(u4[0], _xv.x, v4[0]); \
        accH[0][_nt][1] = fmaf(u4[0], _xv.y, v4[0]); \
        accH[0][_nt][2] = fmaf(u4[1], _xv.x, v4[1]); \
        accH[0][_nt][3] = fmaf(u4[1], _xv.y, v4[1]); \
        accH[1][_nt][0] = fmaf(u4[2], _xv.x, v4[2]); \
        accH[1][_nt][1] = fmaf(u4[2], _xv.y, v4[2]); \
        accH[1][_nt][2] = fmaf(u4[3], _xv.x, v4[3]); \
        accH[1][_nt][3] = fmaf(u4[3], _xv.y, v4[3]); \
    } \
} while (0)

#define MMA_HALF(accH, parity, colOff) do { \
    uint32_t _hRd = sb_h + (uint32_t)(parity) * 10240u + hLane + (colOff); \
    _Pragma("unroll") \
    for (int _kb = 0; _kb < 8; _kb++) { \
        uint32_t _q0, _q1, _q2, _q3; \
        ldsm4t(_q0, _q1, _q2, _q3, _hRd + (uint32_t)_kb * 1280u); \
        uint32_t _B0[2] = {_q0, _q1}, _B1[2] = {_q2, _q3}; \
        mma_(accH[0][0], A[0][_kb], _B0); \
        mma_(accH[1][0], A[1][_kb], _B0); \
        mma_(accH[0][1], A[0][_kb], _B1); \
        mma_(accH[1][1], A[1][_kb], _B1); \
    } \
} while (0)

#define EPI_HALF(accH, cstH, half, wparity) do { \
    unsigned short* _hw = (unsigned short*)(dsm + SHH_OFF) + (size_t)(wparity) * 5120; \
    _Pragma("unroll") \
    for (int _nt = 0; _nt < 2; _nt++) { \
        unsigned _si = sig2(f16x2pk(accH[0][_nt][0], accH[0][_nt][1])); \
        unsigned _sf = sig2(f16x2pk(accH[0][_nt][2], accH[0][_nt][3])); \
        unsigned _so = sig2(f16x2pk(accH[1][_nt][2], accH[1][_nt][3])); \
        float _tg0 = tanha(accH[1][_nt][0]); \
        float _tg1 = tanha(accH[1][_nt][1]); \
        float _si0, _si1, _sf0, _sf1, _so0, _so1; \
        up2(_si, _si0, _si1); \
        up2(_sf, _sf0, _sf1); \
        up2(_so, _so0, _so1); \
        float _c20 = _sf0 * cstH[_nt * 2 + 0] + _si0 * _tg0; \
        float _c21 = _sf1 * cstH[_nt * 2 + 1] + _si1 * _tg1; \
        float _h0  = _so0 * tanha(_c20); \
        float _h1  = _so1 * tanha(_c21); \
        cstH[_nt * 2 + 0] = _c20; cstH[_nt * 2 + 1] = _c21; \
        *(unsigned*)&_hw[u * 40 + ((half) * 2 + _nt) * 8 + 2 * lm4] = f16x2pk(_h0, _h1); \
    } \
} while (0)

__global__ void __launch_bounds__(THR, 1) k_lstm(const float* __restrict__ bfh) {
    extern __shared__ char dsm[];

    const int tid = threadIdx.x;
    const int lid = tid & 31;
    const int w   = tid >> 5;
    const int lid4 = lid >> 2, lm4 = lid & 3;
    const int rl  = (lid & 7) | (((lid >> 3) & 1) << 3);
    const int ch  = lid >> 4;
    const int u   = 8 * w + lid4;                /* this thread's hidden unit */
    const int gab = blockIdx.x * 32;

    /* ---- A fragments of W_hh, loaded ONCE from global (64 regs) ---- */
    uint32_t A[2][8][4];
    #pragma unroll
    for (int mt = 0; mt < 2; mt++)
        #pragma unroll
        for (int kb = 0; kb < 8; kb++) {
            const unsigned short* r0 = &d_W16[((2 * mt)     * 128 + u) * 128 + kb * 16 + 2 * lm4];
            const unsigned short* r1 = &d_W16[((2 * mt + 1) * 128 + u) * 128 + kb * 16 + 2 * lm4];
            A[mt][kb][0] = *(const uint32_t*)r0;
            A[mt][kb][1] = *(const uint32_t*)r1;
            A[mt][kb][2] = *(const uint32_t*)(r0 + 8);
            A[mt][kb][3] = *(const uint32_t*)(r1 + 8);
        }

    float u4[4], v4[4];
    #pragma unroll
    for (int b = 0; b < 4; b++) { u4[b] = d_u[b * 128 + u]; v4[b] = d_v[b * 128 + u]; }

    float cstA[4], cstB[4];
    #pragma unroll
    for (int i = 0; i < 4; i++) { cstA[i] = 0.0f; cstB[i] = 0.0f; }

    /* zero h read-buffer 0; stage this block's whole X tile into smem */
    for (int p = tid; p < 2560; p += THR)
        ((uint32_t*)(dsm + SHH_OFF))[p] = 0u;
    {
        float* sxf = (float*)(dsm + SX_OFF);
        for (int i = tid; i < 4096; i += THR)
            sxf[i] = d_Xt[(i >> 5) * KN + gab + (i & 31)];
    }
    __syncthreads();

    const uint32_t sb_h = smem_u32(dsm + SHH_OFF);
    const uint32_t hLane = (uint32_t)rl * 80 + (uint32_t)ch * 16;
    const float2* sx2 = (const float2*)(dsm + SX_OFF);

    float accA[2][2][4], accB[2][2][4];

    /* prologue: step 0 */
    INIT_ACC(accA, 0, 0); MMA_HALF(accA, 0, 0u);  /* MMA_A(0) reads buf0 (zeros) */
    __syncthreads();                               /* barB */
    INIT_ACC(accB, 1, 0); MMA_HALF(accB, 0, 32u); /* MMA_B(0) */
    EPI_HALF(accA, cstA, 0, 1);                   /* EPI_A(0) -> buf1 cols A */

    for (int t = 1; t < LN; t++) {
        __syncthreads();                           /* barA: h_A(t-1) complete */
        INIT_ACC(accA, 0, t);
        MMA_HALF(accA, t & 1, 0u);                /* MMA_A(t), async on tensor */
        EPI_HALF(accB, cstB, 1, t & 1);           /* EPI_B(t-1), overlaps MMA_A */
        __syncthreads();                           /* barB: h_B(t-1) complete */
        INIT_ACC(accB, 1, t);
        MMA_HALF(accB, t & 1, 32u);               /* MMA_B(t), async on tensor */
        EPI_HALF(accA, cstA, 0, (t & 1) ^ 1);     /* EPI_A(t), overlaps MMA_B */
    }
    EPI_HALF(accB, cstB, 1, 0);                   /* tail: EPI_B(127) -> buf0 */
    __syncthreads();                               /* final h (both halves) in buf0 */

    /* ---- stage c to smem for the f-gate pass ---- */
    float* shc = (float*)(dsm + SHC_OFF);
    #pragma unroll
    for (int nt = 0; nt < 2; nt++) {
        shc[u * 33 + nt * 8 + 2 * lm4]          = cstA[nt * 2 + 0];
        shc[u * 33 + nt * 8 + 2 * lm4 + 1]      = cstA[nt * 2 + 1];
        shc[u * 33 + 16 + nt * 8 + 2 * lm4]     = cstB[nt * 2 + 0];
        shc[u * 33 + 16 + nt * 8 + 2 * lm4 + 1] = cstB[nt * 2 + 1];
    }
    __syncthreads();

    /* ---- f-gate GEMM: warp w -> m16 tile (w&7), n-half (w>>3) ---- */
    const int mt = w & 7, nh = w >> 3;
    uint32_t Af[8][4];
    #pragma unroll
    for (int kb = 0; kb < 8; kb++) {
        const unsigned short* r0 = &d_Wf16[(16 * mt + lid4) * 128 + kb * 16 + 2 * lm4];
        const unsigned short* r1 = r0 + 8 * 128;
        Af[kb][0] = *(const uint32_t*)r0;
        Af[kb][1] = *(const uint32_t*)r1;
        Af[kb][2] = *(const uint32_t*)(r0 + 8);
        Af[kb][3] = *(const uint32_t*)(r1 + 8);
    }
    float fa[2][4];
    #pragma unroll
    for (int nt = 0; nt < 2; nt++)
        #pragma unroll
        for (int q = 0; q < 4; q++) fa[nt][q] = 0.0f;
    const uint32_t hF = sb_h + hLane + (uint32_t)nh * 32;   /* final h in buffer 0 */
    #pragma unroll
    for (int kb = 0; kb < 8; kb++) {
        uint32_t q0, q1, q2, q3;
        ldsm4t(q0, q1, q2, q3, hF + (uint32_t)kb * 1280);
        uint32_t B0[2] = {q0, q1}, B1[2] = {q2, q3};
        mma_(fa[0], Af[kb], B0);
        mma_(fa[1], Af[kb], B1);
    }
    const int r0 = 16 * mt + lid4, r1 = r0 + 8;
    float b0 = bfh[r0], b1 = bfh[r1];
    float f0 = 0.0f, f1 = 0.0f;
    #pragma unroll
    for (int nt = 0; nt < 2; nt++)
        #pragma unroll
        for (int q = 0; q < 2; q++) {
            int col = nh * 16 + nt * 8 + 2 * lm4 + q;
            f0 += sigf(fa[nt][q]     + b0) * shc[r0 * 33 + col];
            f1 += sigf(fa[nt][2 + q] + b1) * shc[r1 * 33 + col];
        }
    f0 += __shfl_xor_sync(0xFFFFFFFFu, f0, 1);
    f0 += __shfl_xor_sync(0xFFFFFFFFu, f0, 2);
    f1 += __shfl_xor_sync(0xFFFFFFFFu, f1, 1);
    f1 += __shfl_xor_sync(0xFFFFFFFFu, f1, 2);
    float* shred = (float*)(dsm + SHRED_OFF);
    if (lm4 == 0) { shred[nh * 128 + r0] = f0; shred[nh * 128 + r1] = f1; }
    __syncthreads();

    if (tid < 128) {
        float fc = shred[tid] + shred[128 + tid];
        float hs = 0.0f;
        const unsigned short* h0 = (const unsigned short*)(dsm + SHH_OFF);
        #pragma unroll 8
        for (int a = 0; a < 32; a++) hs += f16tof(h0[tid * 40 + a]);
        d_fcp[blockIdx.x * MEM + tid] = fc;
        d_hsp[blockIdx.x * MEM + tid] = hs;
    }
}

/* -------- 5) final tree-LSTM root math -------- */
__global__ void k_final(const float* __restrict__ Wiou, const float* __restrict__ biou,
                        const float* __restrict__ Wlout, const float* __restrict__ blout,
                        float* __restrict__ out) {
    __shared__ float sh_hs[128];
    __shared__ float sh_h[128];
    int k = threadIdx.x;
    float fc = 0.0f, hs = 0.0f;
    for (int b = 0; b < NBLK; b++) {
        fc += d_fcp[b * MEM + k];
        hs += d_hsp[b * MEM + k];
    }
    sh_hs[k] = hs;
    __syncthreads();
    float iv = biou[k], ov = biou[128 + k], uv = biou[256 + k];
    #pragma unroll 8
    for (int j = 0; j < 128; j++) {
        float h = sh_hs[j];
        iv += Wiou[k * 128 + j] * h;
        ov += Wiou[(128 + k) * 128 + j] * h;
        uv += Wiou[(256 + k) * 128 + j] * h;
    }
    float cv = sigf(iv) * tanh_(uv) + fc;
    float hv = sigf(ov) * tanh_(cv);
    out[k]  = cv;
    sh_h[k] = hv;
    __syncthreads();
    float acc = blout[k];
    #pragma unroll 8
    for (int j = 0; j < 128; j++) acc += Wlout[k * 128 + j] * sh_h[j];
    out[128 + k] = acc;
}

extern "C" void kernel_launch(void* const* d_in, const int* in_sizes, int n_in,
                              void* d_out, int out_size) {
    const float* numbers = (const float*)d_in[0];
    const float* wnum    = (const float*)d_in[1];
    const float* bnum    = (const float*)d_in[2];
    const float* Wih     = (const float*)d_in[3];
    const float* Whh     = (const float*)d_in[4];
    const float* bih     = (const float*)d_in[5];
    const float* bhh     = (const float*)d_in[6];
    const float* Wfh     = (const float*)d_in[7];
    const float* bfh     = (const float*)d_in[8];
    const float* Wiou    = (const float*)d_in[9];
    const float* biou    = (const float*)d_in[10];
    const float* Wlout   = (const float*)d_in[11];
    const float* blout   = (const float*)d_in[12];
    float* out = (float*)d_out;

    cudaFuncSetAttribute(k_lstm, cudaFuncAttributeMaxDynamicSharedMemorySize, SMEM_TOTAL);

    k_stats<<<1, 128>>>(numbers);
    k_norm<<<(KN * LN + 255) / 256, 256>>>(numbers);
    k_prep<<<(G4 * MEM + MEM * MEM + G4 + 255) / 256, 256>>>(Wih, Whh, bih, bhh, Wfh, wnum, bnum);
    k_lstm<<<NBLK, THR, SMEM_TOTAL>>>(bfh);
    k_final<<<1, 128>>>(Wiou, biou, Wlout, blout, out);
}

// round 16
// speedup vs baseline: 1.2078x; 1.0607x over previous
#include <cuda_runtime.h>
#include <cstdint>

#define KN   4096
#define LN   128
#define MEM  128
#define G4   512
#define NBLK 128
#define THR  512           /* 16 warps, 32 arrays, halves pipelined */

/* dynamic smem layout (bytes) */
#define SHH_OFF  0          /* 20480: h f16 [2 buf][128 unit][40 pad arrays] */
#define SX_OFF   20480      /* 16384: x tile f32 [128 step][32 array] */
#define SHC_OFF  36864      /* 16896: final c [128][33] */
#define SHRED_OFF 53760     /* 1024 : f-gate partial reduction [2][128] */
#define SMEM_TOTAL 54784

/* ---------------- device scratch ---------------- */
__device__ unsigned short d_W16[G4 * MEM];    /* f16(W_hh) row-major [gate row g][j] */
__device__ unsigned short d_Wf16[MEM * MEM];  /* f16(W_fh) */
__device__ float d_u[G4], d_v[G4];
__device__ float d_tabm[100], d_tabi[100], d_gm, d_gi;
__device__ float d_fcp[NBLK * MEM], d_hsp[NBLK * MEM];

/* ---------------- helpers ---------------- */
__device__ __forceinline__ uint32_t smem_u32(const void* p) {
    uint32_t a;
    asm("{ .reg .u64 t; cvta.to.shared.u64 t, %1; cvt.u32.u64 %0, t; }" : "=r"(a) : "l"(p));
    return a;
}
__device__ __forceinline__ float frcp(float x) { float r; asm("rcp.approx.f32 %0, %1;" : "=f"(r) : "f"(x)); return r; }
__device__ __forceinline__ float sigf(float x) { return frcp(1.0f + __expf(-x)); }
__device__ __forceinline__ float tanh_(float x) {
    float ax = fabsf(x);
    float e  = __expf(-2.0f * ax);
    float r  = (1.0f - e) * frcp(1.0f + e);
    return copysignf(r, x);
}
__device__ __forceinline__ float tanha(float x) {
    float r; asm("tanh.approx.f32 %0, %1;" : "=f"(r) : "f"(x)); return r;
}
/* packed f16x2 ops */
__device__ __forceinline__ unsigned tanh2(unsigned x) {
    unsigned r; asm("tanh.approx.f16x2 %0, %1;" : "=r"(r) : "r"(x)); return r;
}
__device__ __forceinline__ unsigned sig2(unsigned x) {   /* 0.5*tanh(0.5x)+0.5 */
    const unsigned H2 = 0x38003800u;
    unsigned t;
    asm("mul.rn.f16x2 %0, %1, %2;" : "=r"(t) : "r"(x), "r"(H2));
    t = tanh2(t);
    unsigned r;
    asm("fma.rn.f16x2 %0, %1, %2, %2;" : "=r"(r) : "r"(t), "r"(H2));
    return r;
}
__device__ __forceinline__ unsigned mul2(unsigned a, unsigned b) {
    unsigned r; asm("mul.rn.f16x2 %0, %1, %2;" : "=r"(r) : "r"(a), "r"(b)); return r;
}
__device__ __forceinline__ void up2(unsigned p, float& lo, float& hi) {
    asm("{ .reg .b16 a,b; mov.b32 {a,b}, %2; cvt.f32.f16 %0, a; cvt.f32.f16 %1, b; }"
        : "=f"(lo), "=f"(hi) : "r"(p));
}
__device__ __forceinline__ unsigned short f16b(float f) {
    unsigned short u; asm("cvt.rn.f16.f32 %0, %1;" : "=h"(u) : "f"(f)); return u;
}
__device__ __forceinline__ float f16tof(unsigned short u) {
    float f; asm("cvt.f32.f16 %0, %1;" : "=f"(f) : "h"(u)); return f;
}
__device__ __forceinline__ unsigned f16x2pk(float lo, float hi) {
    unsigned r; asm("cvt.rn.f16x2.f32 %0, %1, %2;" : "=r"(r) : "f"(hi), "f"(lo)); return r;
}
__device__ __forceinline__ void ldsm4t(uint32_t& r0, uint32_t& r1, uint32_t& r2, uint32_t& r3, uint32_t a) {
    asm volatile("ldmatrix.sync.aligned.m8n8.x4.trans.shared.b16 {%0,%1,%2,%3}, [%4];"
                 : "=r"(r0), "=r"(r1), "=r"(r2), "=r"(r3) : "r"(a));
}
__device__ __forceinline__ void mma_(float* d, const uint32_t* a, const uint32_t* b) {
    asm volatile("mma.sync.aligned.m16n8k16.row.col.f32.f16.f16.f32 "
                 "{%0,%1,%2,%3},{%4,%5,%6,%7},{%8,%9},{%0,%1,%2,%3};"
                 : "+f"(d[0]), "+f"(d[1]), "+f"(d[2]), "+f"(d[3])
                 : "r"(a[0]), "r"(a[1]), "r"(a[2]), "r"(a[3]), "r"(b[0]), "r"(b[1]));
}

/* -------- 1) weight prep + (in last block) running stats -------- */
__global__ void k_prep(const float* __restrict__ Wih, const float* __restrict__ Whh,
                       const float* __restrict__ bih, const float* __restrict__ bhh,
                       const float* __restrict__ Wfh, const float* __restrict__ wnum,
                       const float* __restrict__ bnum, const float* __restrict__ nums) {
    __shared__ float s[100], scs[100], scss[100];
    int idx = blockIdx.x * blockDim.x + threadIdx.x;
    if (blockIdx.x == gridDim.x - 1) {           /* dedicated stats block */
        int t = threadIdx.x;
        if (t < 100) s[t] = nums[t];
        __syncthreads();
        if (t == 0) {
            float cs = 0.0f, css = 0.0f;
            #pragma unroll 4
            for (int i = 0; i < 100; i++) {
                float x = s[i];
                cs += x; css += x * x;
                scs[i] = cs; scss[i] = css;
            }
        }
        __syncthreads();
        if (t < 100) {
            float cap  = (float)(t + 1);
            float mean = scs[t] / cap;
            float var  = fmaxf(scss[t] / cap - mean * mean, 0.0f);
            float sd   = sqrtf(var);
            bool  use  = (cap > 3.0f) && (sd > 1e-8f);
            float inv  = use ? (1.0f / sd) : 1.0f;
            d_tabm[t] = mean; d_tabi[t] = inv;
            if (t == 99) { d_gm = mean; d_gi = inv; }
        }
        return;
    }
    if (idx < G4 * MEM) d_W16[idx] = f16b(Whh[idx]);
    int i2 = idx - G4 * MEM;
    if (i2 >= 0 && i2 < MEM * MEM) d_Wf16[i2] = f16b(Wfh[i2]);
    int i3 = idx - G4 * MEM - MEM * MEM;
    if (i3 >= 0 && i3 < G4) {
        const float* row = Wih + i3 * 256 + 128;
        float u = 0.0f, v = 0.0f;
        #pragma unroll 8
        for (int j = 0; j < 128; j++) { u += row[j] * wnum[j]; v += row[j] * bnum[j]; }
        d_u[i3] = u;
        d_v[i3] = v + bih[i3] + bhh[i3];
    }
}

/* -------- 2) main LSTM: register-resident W, half-step pipelined halves -------- */
/* warp w owns hidden units 8w..8w+8, all 4 gate banks. Thread (lid4,lm4) holds the
   full (i,f,g,o) quadruple for unit u=8w+lid4, arrays {half*16 + ntl*8 + 2lm4, +1}.
   Accumulators initialized with exact fp32 input term u*x+v; MMA adds W_hh@h.
   h = sig(o) * tanh(c) computed fully packed f16x2 (h is stored f16 anyway). */

#define INIT_ACC(accH, half, tt) do { \
    _Pragma("unroll") \
    for (int _nt = 0; _nt < 2; _nt++) { \
        float2 _xv = sx2[(tt) * 16 + (half) * 8 + _nt * 4 + lm4]; \
        accH[0][_nt][0] = fmaf(u4[0], _xv.x, v4[0]); \
        accH[0][_nt][1] = fmaf(u4[0], _xv.y, v4[0]); \
        accH[0][_nt][2] = fmaf(u4[1], _xv.x, v4[1]); \
        accH[0][_nt][3] = fmaf(u4[1], _xv.y, v4[1]); \
        accH[1][_nt][0] = fmaf(u4[2], _xv.x, v4[2]); \
        accH[1][_nt][1] = fmaf(u4[2], _xv.y, v4[2]); \
        accH[1][_nt][2] = fmaf(u4[3], _xv.x, v4[3]); \
        accH[1][_nt][3] = fmaf(u4[3], _xv.y, v4[3]); \
    } \
} while (0)

#define MMA_HALF(accH, parity, colOff) do { \
    uint32_t _hRd = sb_h + (uint32_t)(parity) * 10240u + hLane + (colOff); \
    _Pragma("unroll") \
    for (int _kb = 0; _kb < 8; _kb++) { \
        uint32_t _q0, _q1, _q2, _q3; \
        ldsm4t(_q0, _q1, _q2, _q3, _hRd + (uint32_t)_kb * 1280u); \
        uint32_t _B0[2] = {_q0, _q1}, _B1[2] = {_q2, _q3}; \
        mma_(accH[0][0], A[0][_kb], _B0); \
        mma_(accH[1][0], A[1][_kb], _B0); \
        mma_(accH[0][1], A[0][_kb], _B1); \
        mma_(accH[1][1], A[1][_kb], _B1); \
    } \
} while (0)

#define EPI_HALF(accH, cstH, half, wparity) do { \
    unsigned short* _hw = (unsigned short*)(dsm + SHH_OFF) + (size_t)(wparity) * 5120; \
    _Pragma("unroll") \
    for (int _nt = 0; _nt < 2; _nt++) { \
        unsigned _si = sig2(f16x2pk(accH[0][_nt][0], accH[0][_nt][1])); \
        unsigned _sf = sig2(f16x2pk(accH[0][_nt][2], accH[0][_nt][3])); \
        unsigned _so = sig2(f16x2pk(accH[1][_nt][2], accH[1][_nt][3])); \
        float _tg0 = tanha(accH[1][_nt][0]); \
        float _tg1 = tanha(accH[1][_nt][1]); \
        float _si0, _si1, _sf0, _sf1; \
        up2(_si, _si0, _si1); \
        up2(_sf, _sf0, _sf1); \
        float _c20 = _sf0 * cstH[_nt * 2 + 0] + _si0 * _tg0; \
        float _c21 = _sf1 * cstH[_nt * 2 + 1] + _si1 * _tg1; \
        cstH[_nt * 2 + 0] = _c20; cstH[_nt * 2 + 1] = _c21; \
        unsigned _h = mul2(_so, tanh2(f16x2pk(_c20, _c21))); \
        *(unsigned*)&_hw[u * 40 + ((half) * 2 + _nt) * 8 + 2 * lm4] = _h; \
    } \
} while (0)

__global__ void __launch_bounds__(THR, 1) k_lstm(const float* __restrict__ bfh,
                                                 const float* __restrict__ nums) {
    extern __shared__ char dsm[];

    const int tid = threadIdx.x;
    const int lid = tid & 31;
    const int w   = tid >> 5;
    const int lid4 = lid >> 2, lm4 = lid & 3;
    const int rl  = (lid & 7) | (((lid >> 3) & 1) << 3);
    const int ch  = lid >> 4;
    const int u   = 8 * w + lid4;                /* this thread's hidden unit */
    const int gab = blockIdx.x * 32;

    /* ---- A fragments of W_hh, loaded ONCE from global (64 regs) ---- */
    uint32_t A[2][8][4];
    #pragma unroll
    for (int mt = 0; mt < 2; mt++)
        #pragma unroll
        for (int kb = 0; kb < 8; kb++) {
            const unsigned short* r0 = &d_W16[((2 * mt)     * 128 + u) * 128 + kb * 16 + 2 * lm4];
            const unsigned short* r1 = &d_W16[((2 * mt + 1) * 128 + u) * 128 + kb * 16 + 2 * lm4];
            A[mt][kb][0] = *(const uint32_t*)r0;
            A[mt][kb][1] = *(const uint32_t*)r1;
            A[mt][kb][2] = *(const uint32_t*)(r0 + 8);
            A[mt][kb][3] = *(const uint32_t*)(r1 + 8);
        }

    float u4[4], v4[4];
    #pragma unroll
    for (int b = 0; b < 4; b++) { u4[b] = d_u[b * 128 + u]; v4[b] = d_v[b * 128 + u]; }

    float cstA[4], cstB[4];
    #pragma unroll
    for (int i = 0; i < 4; i++) { cstA[i] = 0.0f; cstB[i] = 0.0f; }

    /* zero h read-buffer 0; stage + normalize this block's X tile from raw numbers */
    for (int p = tid; p < 2560; p += THR)
        ((uint32_t*)(dsm + SHH_OFF))[p] = 0u;
    {
        float* sxf = (float*)(dsm + SX_OFF);
        float gm = d_gm, gi = d_gi;
        for (int i = tid; i < 4096; i += THR) {
            int t = i >> 5, a = i & 31;
            int flat = (gab + a) * 128 + t;
            float x = nums[flat];
            float m = gm, inv = gi;
            if (flat < 100) { m = d_tabm[flat]; inv = d_tabi[flat]; }
            sxf[i] = (x - m) * inv;     /* sxf[t*32 + a] */
        }
    }
    __syncthreads();

    const uint32_t sb_h = smem_u32(dsm + SHH_OFF);
    const uint32_t hLane = (uint32_t)rl * 80 + (uint32_t)ch * 16;
    const float2* sx2 = (const float2*)(dsm + SX_OFF);

    float accA[2][2][4], accB[2][2][4];

    /* prologue: step 0 */
    INIT_ACC(accA, 0, 0); MMA_HALF(accA, 0, 0u);  /* MMA_A(0) reads buf0 (zeros) */
    __syncthreads();                               /* barB */
    INIT_ACC(accB, 1, 0); MMA_HALF(accB, 0, 32u); /* MMA_B(0) */
    EPI_HALF(accA, cstA, 0, 1);                   /* EPI_A(0) -> buf1 cols A */

    for (int t = 1; t < LN; t++) {
        __syncthreads();                           /* barA: h_A(t-1) complete */
        INIT_ACC(accA, 0, t);
        MMA_HALF(accA, t & 1, 0u);                /* MMA_A(t), async on tensor */
        EPI_HALF(accB, cstB, 1, t & 1);           /* EPI_B(t-1), overlaps MMA_A */
        __syncthreads();                           /* barB: h_B(t-1) complete */
        INIT_ACC(accB, 1, t);
        MMA_HALF(accB, t & 1, 32u);               /* MMA_B(t), async on tensor */
        EPI_HALF(accA, cstA, 0, (t & 1) ^ 1);     /* EPI_A(t), overlaps MMA_B */
    }
    EPI_HALF(accB, cstB, 1, 0);                   /* tail: EPI_B(127) -> buf0 */
    __syncthreads();                               /* final h (both halves) in buf0 */

    /* ---- stage c to smem for the f-gate pass ---- */
    float* shc = (float*)(dsm + SHC_OFF);
    #pragma unroll
    for (int nt = 0; nt < 2; nt++) {
        shc[u * 33 + nt * 8 + 2 * lm4]          = cstA[nt * 2 + 0];
        shc[u * 33 + nt * 8 + 2 * lm4 + 1]      = cstA[nt * 2 + 1];
        shc[u * 33 + 16 + nt * 8 + 2 * lm4]     = cstB[nt * 2 + 0];
        shc[u * 33 + 16 + nt * 8 + 2 * lm4 + 1] = cstB[nt * 2 + 1];
    }
    __syncthreads();

    /* ---- f-gate GEMM: warp w -> m16 tile (w&7), n-half (w>>3) ---- */
    const int mt = w & 7, nh = w >> 3;
    uint32_t Af[8][4];
    #pragma unroll
    for (int kb = 0; kb < 8; kb++) {
        const unsigned short* r0 = &d_Wf16[(16 * mt + lid4) * 128 + kb * 16 + 2 * lm4];
        const unsigned short* r1 = r0 + 8 * 128;
        Af[kb][0] = *(const uint32_t*)r0;
        Af[kb][1] = *(const uint32_t*)r1;
        Af[kb][2] = *(const uint32_t*)(r0 + 8);
        Af[kb][3] = *(const uint32_t*)(r1 + 8);
    }
    float fa[2][4];
    #pragma unroll
    for (int nt = 0; nt < 2; nt++)
        #pragma unroll
        for (int q = 0; q < 4; q++) fa[nt][q] = 0.0f;
    const uint32_t hF = sb_h + hLane + (uint32_t)nh * 32;   /* final h in buffer 0 */
    #pragma unroll
    for (int kb = 0; kb < 8; kb++) {
        uint32_t q0, q1, q2, q3;
        ldsm4t(q0, q1, q2, q3, hF + (uint32_t)kb * 1280);
        uint32_t B0[2] = {q0, q1}, B1[2] = {q2, q3};
        mma_(fa[0], Af[kb], B0);
        mma_(fa[1], Af[kb], B1);
    }
    const int r0 = 16 * mt + lid4, r1 = r0 + 8;
    float b0 = bfh[r0], b1 = bfh[r1];
    float f0 = 0.0f, f1 = 0.0f;
    #pragma unroll
    for (int nt = 0; nt < 2; nt++)
        #pragma unroll
        for (int q = 0; q < 2; q++) {
            int col = nh * 16 + nt * 8 + 2 * lm4 + q;
            f0 += sigf(fa[nt][q]     + b0) * shc[r0 * 33 + col];
            f1 += sigf(fa[nt][2 + q] + b1) * shc[r1 * 33 + col];
        }
    f0 += __shfl_xor_sync(0xFFFFFFFFu, f0, 1);
    f0 += __shfl_xor_sync(0xFFFFFFFFu, f0, 2);
    f1 += __shfl_xor_sync(0xFFFFFFFFu, f1, 1);
    f1 += __shfl_xor_sync(0xFFFFFFFFu, f1, 2);
    float* shred = (float*)(dsm + SHRED_OFF);
    if (lm4 == 0) { shred[nh * 128 + r0] = f0; shred[nh * 128 + r1] = f1; }
    __syncthreads();

    if (tid < 128) {
        float fc = shred[tid] + shred[128 + tid];
        float hs = 0.0f;
        const unsigned short* h0 = (const unsigned short*)(dsm + SHH_OFF);
        #pragma unroll 8
        for (int a = 0; a < 32; a++) hs += f16tof(h0[tid * 40 + a]);
        d_fcp[blockIdx.x * MEM + tid] = fc;
        d_hsp[blockIdx.x * MEM + tid] = hs;
    }
}

/* -------- 3) final tree-LSTM root math -------- */
__global__ void k_final(const float* __restrict__ Wiou, const float* __restrict__ biou,
                        const float* __restrict__ Wlout, const float* __restrict__ blout,
                        float* __restrict__ out) {
    __shared__ float sh_hs[128];
    __shared__ float sh_h[128];
    int k = threadIdx.x;
    float fc = 0.0f, hs = 0.0f;
    for (int b = 0; b < NBLK; b++) {
        fc += d_fcp[b * MEM + k];
        hs += d_hsp[b * MEM + k];
    }
    sh_hs[k] = hs;
    __syncthreads();
    float iv = biou[k], ov = biou[128 + k], uv = biou[256 + k];
    #pragma unroll 8
    for (int j = 0; j < 128; j++) {
        float h = sh_hs[j];
        iv += Wiou[k * 128 + j] * h;
        ov += Wiou[(128 + k) * 128 + j] * h;
        uv += Wiou[(256 + k) * 128 + j] * h;
    }
    float cv = sigf(iv) * tanh_(uv) + fc;
    float hv = sigf(ov) * tanh_(cv);
    out[k]  = cv;
    sh_h[k] = hv;
    __syncthreads();
    float acc = blout[k];
    #pragma unroll 8
    for (int j = 0; j < 128; j++) acc += Wlout[k * 128 + j] * sh_h[j];
    out[128 + k] = acc;
}

extern "C" void kernel_launch(void* const* d_in, const int* in_sizes, int n_in,
                              void* d_out, int out_size) {
    const float* numbers = (const float*)d_in[0];
    const float* wnum    = (const float*)d_in[1];
    const float* bnum    = (const float*)d_in[2];
    const float* Wih     = (const float*)d_in[3];
    const float* Whh     = (const float*)d_in[4];
    const float* bih     = (const float*)d_in[5];
    const float* bhh     = (const float*)d_in[6];
    const float* Wfh     = (const float*)d_in[7];
    const float* bfh     = (const float*)d_in[8];
    const float* Wiou    = (const float*)d_in[9];
    const float* biou    = (const float*)d_in[10];
    const float* Wlout   = (const float*)d_in[11];
    const float* blout   = (const float*)d_in[12];
    float* out = (float*)d_out;

    cudaFuncSetAttribute(k_lstm, cudaFuncAttributeMaxDynamicSharedMemorySize, SMEM_TOTAL);

    /* prep covers G4*MEM + MEM*MEM + G4 = 82432 elems = 322 blocks; +1 stats block */
    k_prep<<<323, 256>>>(Wih, Whh, bih, bhh, Wfh, wnum, bnum, numbers);
    k_lstm<<<NBLK, THR, SMEM_TOTAL>>>(bfh, numbers);
    k_final<<<1, 128>>>(Wiou, biou, Wlout, blout, out);
}